// round 14
// baseline (speedup 1.0000x reference)
#include <cuda_runtime.h>

typedef unsigned long long u64;
typedef unsigned int uint32;

#define HH 8
#define NNS 1024
#define DD 64
#define MM 128
#define CC 64
#define NCH 16
#define EPSF 1e-3f
#define NORMF 0.35355339059327373f   // 64^-0.25

// ---- global scratch ----
__device__ float g_Sc[HH*NCH*MM*DD];   // per-chunk Kp^T V (fp32, 4 MB)
__device__ float g_zc[HH*NCH*MM];      // per-chunk kp column sums
__device__ int   g_flagZ[HH*NCH];      // z_c published (zero-init; deterministic re-publish)
__device__ int   g_flagS[HH*NCH];      // S_c published

// strides: ≡ 8 (mod 32) -> uint2 fragment loads are bank-conflict-free
#define S128 136
#define S64  72

// ---- smem layout (float offsets) ----
#define OFF_QI   0                     // q'  [n=64][off128(m)]   8704
#define OFF_KPA  8704                  // kp  [m=128][off64(n)]   9216 -> 17920
#define OFF_KPB  17920                 // kp  [n=64][off128(m)]   8704 -> 26624
#define OFF_VI   26624                 // v   [d=64][off64(n)]    4608 -> 31232
#define OFF_SEG  31232                 // seg sums [4][128]        512 -> 32256 (alloc 1024)
#define OFF_ZQ   32256                 // z prefix partials [4][128] 512 -> 32768
#define OFF_D    32768
// phase1 view:
#define OFF_PSI  (OFF_D)               // proj [m=128][off64(d)]  9216
#define OFF_XQI  (OFF_D+9216)          // q*norm [n=64][off64(d)] 4608
#define OFF_XKI  (OFF_D+13824)         // k*norm [n=64][off64(d)] 4608
// post-join view:
#define OFF_SSI  (OFF_D)               // S_prev [d=64][off128(m)] 8704
#define OFF_ASI  (OFF_D+8704)          // A [n=64][off64(j)]      4608
#define OFF_OB   (OFF_D+13312)         // out2 [64][72]           4608
#define SMEMF    (OFF_D+18432)         // 51200 floats = 204800 B

#define F2U __float_as_uint
#define U2F __uint_as_float

#define BARSYNC(id, cnt)   asm volatile("bar.sync %0, %1;"   :: "r"(id), "r"(cnt) : "memory")
#define BARARRIVE(id, cnt) asm volatile("bar.arrive %0, %1;" :: "r"(id), "r"(cnt) : "memory")

__device__ __forceinline__ int koff(int k) {
    return ((k >> 3) << 3) | ((k & 3) << 1) | ((k >> 2) & 1);
}
__device__ __forceinline__ float tf32r(float f) {
    uint32 u; asm("cvt.rna.tf32.f32 %0,%1;" : "=r"(u) : "f"(f));
    return U2F(u);
}
__device__ __forceinline__ u64 pk2(float x, float y) {
    u64 r; asm("mov.b64 %0,{%1,%2};" : "=l"(r) : "f"(x), "f"(y)); return r;
}
// D += A*B  (m16n8k8, row.col, tf32 in / f32 acc)
__device__ __forceinline__ void mma8(float* c, uint32 a0, uint32 a1, uint32 a2, uint32 a3,
                                     uint32 b0, uint32 b1) {
    asm volatile("mma.sync.aligned.m16n8k8.row.col.f32.tf32.tf32.f32 "
        "{%0,%1,%2,%3},{%4,%5,%6,%7},{%8,%9},{%0,%1,%2,%3};"
        : "+f"(c[0]), "+f"(c[1]), "+f"(c[2]), "+f"(c[3])
        : "r"(a0), "r"(a1), "r"(a2), "r"(a3), "r"(b0), "r"(b1));
}

__global__ void __launch_bounds__(1024, 1)
k_fused(const float* __restrict__ q, const float* __restrict__ k,
        const float* __restrict__ v, const float* __restrict__ proj,
        float* __restrict__ out) {
    extern __shared__ float sm[];
    const int c = blockIdx.x, h = blockIdx.y, tid = threadIdx.x;

    float* qI  = sm + OFF_QI;
    float* kpA = sm + OFF_KPA;
    float* kpB = sm + OFF_KPB;
    float* vI  = sm + OFF_VI;
    float* seg = sm + OFF_SEG;
    float* zq  = sm + OFF_ZQ;
    float* psI = sm + OFF_PSI;
    float* xqI = sm + OFF_XQI;
    float* xkI = sm + OFF_XKI;
    float* SsI = sm + OFF_SSI;
    float* AsI = sm + OFF_ASI;
    float* ob  = sm + OFF_OB;

    const int base = (h*NNS + c*CC)*DD;
    const int w = tid >> 5, lane = tid & 31;
    const int gid = lane >> 2, tig = lane & 3;

    // ================= phase 0: loads (tf32-rounded, interleaved) =================
    for (int i = tid; i < MM*DD; i += 1024) {
        int m = i >> 6, d = i & 63;
        psI[m*S64 + koff(d)] = tf32r(proj[i]);
    }
    for (int i = tid; i < CC*DD; i += 1024) {
        int n = i >> 6, d = i & 63;
        xqI[n*S64 + koff(d)] = tf32r(q[base + i] * NORMF);
        xkI[n*S64 + koff(d)] = tf32r(k[base + i] * NORMF);
        vI[d*S64 + koff(n)]  = tf32r(v[base + i]);
    }
    __syncthreads();

    // =================== warp-specialized middle section ===================
    if (w < 16) {
        // ---------------- Q-side (warps 0-15, tids 0-511) ----------------
        // phase 1q: qp[m][n] -> qI [n][off128(m)]
        {
            const int m0 = 16*(w >> 1), nb = 32*(w & 1);
            float acc[4][4];
            #pragma unroll
            for (int t = 0; t < 4; t++)
                #pragma unroll
                for (int i = 0; i < 4; i++) acc[t][i] = 0.f;
            #pragma unroll
            for (int kk = 0; kk < 8; kk++) {
                const int o = 8*kk + 2*tig;
                uint2 L0 = *(const uint2*)&psI[(m0+gid)*S64   + o];
                uint2 L1 = *(const uint2*)&psI[(m0+gid+8)*S64 + o];
                #pragma unroll
                for (int t = 0; t < 4; t++) {
                    uint2 B = *(const uint2*)&xqI[(nb+8*t+gid)*S64 + o];
                    mma8(acc[t], L0.x, L1.x, L0.y, L1.y, B.x, B.y);
                }
            }
            const int cm  = koff(m0 + gid);
            const int cm8 = cm + 8;
            #pragma unroll
            for (int t = 0; t < 4; t++) {
                const int n0 = nb + 8*t + 2*tig;
                qI[n0*S128     + cm]  = tf32r(fmaxf(acc[t][0], 0.f) + EPSF);
                qI[(n0+1)*S128 + cm]  = tf32r(fmaxf(acc[t][1], 0.f) + EPSF);
                qI[n0*S128     + cm8] = tf32r(fmaxf(acc[t][2], 0.f) + EPSF);
                qI[(n0+1)*S128 + cm8] = tf32r(fmaxf(acc[t][3], 0.f) + EPSF);
            }
        }
        // join with K-side: kpB + seg ready after this; K proceeds to phase 2
        BARSYNC(3, 1024);
        // poll z-flags of earlier chunks (set before their phase 2)
        if (tid < c) {
            while (atomicAdd(&g_flagZ[h*NCH + tid], 0) == 0) {}
        }
        BARSYNC(5, 512);
        __threadfence();
        // z prefix (4-way over 512 threads)
        {
            const int m = tid & 127, qtr = tid >> 7;
            float z = 0.f;
            for (int c2 = qtr; c2 < c; c2 += 4)
                z += g_zc[(h*NCH + c2)*MM + m];
            zq[qtr*128 + m] = z;
        }
        BARSYNC(5, 512);
        // ordered cumsum + divide: 4 segments x 16 n (kpB rows: conflict-free)
        {
            const int m = tid & 127, qtr = tid >> 7;
            const int cm = koff(m);
            float run = zq[m] + zq[128 + m] + zq[256 + m] + zq[384 + m];
            #pragma unroll
            for (int s = 0; s < 3; s++)
                if (s < qtr) run += seg[s*128 + m];
            #pragma unroll
            for (int j = 0; j < 16; j++) {
                const int n = qtr*16 + j;
                run += kpB[n*S128 + cm];
                qI[n*S128 + cm] = tf32r(__fdividef(qI[n*S128 + cm], run));
            }
        }
        BARSYNC(5, 512);                              // qI complete within Q-side
        BARARRIVE(6, 1024);                           // signal qI ready to K-side
        // ---- A = tril(Q'Kp^T)  (mma, k=m, 16 steps), overlapped with K's S_prev ----
        {
            const int n0 = 16*(w & 3), jp = w >> 2;
            float acc[2][4];
            #pragma unroll
            for (int t = 0; t < 2; t++)
                #pragma unroll
                for (int i = 0; i < 4; i++) acc[t][i] = 0.f;
            #pragma unroll 4
            for (int kk = 0; kk < 16; kk++) {
                const int o = 8*kk + 2*tig;
                uint2 L0 = *(const uint2*)&qI[(n0+gid)*S128   + o];
                uint2 L1 = *(const uint2*)&qI[(n0+gid+8)*S128 + o];
                #pragma unroll
                for (int t = 0; t < 2; t++) {
                    const int j0 = 16*jp + 8*t;
                    uint2 B = *(const uint2*)&kpB[(j0+gid)*S128 + o];
                    mma8(acc[t], L0.x, L1.x, L0.y, L1.y, B.x, B.y);
                }
            }
            #pragma unroll
            for (int t = 0; t < 2; t++) {
                const int j = 16*jp + 8*t + 2*tig;
                const int n1 = n0 + gid, n2 = n1 + 8;
                const int cj = koff(j);               // koff(j+1) = cj+2
                AsI[n1*S64 + cj]   = (j   <= n1) ? tf32r(acc[t][0]) : 0.f;
                AsI[n1*S64 + cj+2] = (j+1 <= n1) ? tf32r(acc[t][1]) : 0.f;
                AsI[n2*S64 + cj]   = (j   <= n2) ? tf32r(acc[t][2]) : 0.f;
                AsI[n2*S64 + cj+2] = (j+1 <= n2) ? tf32r(acc[t][3]) : 0.f;
            }
        }
    } else {
        // ---------------- K-side (warps 16-31, tids 512-1023) ----------------
        const int wk = w - 16;
        const int t512 = tid - 512;
        // phase 1k: kp[m][n] -> kpA [m][off64(n)] and kpB [n][off128(m)]
        {
            const int m0 = 16*(wk >> 1), nb = 32*(wk & 1);
            float acc[4][4];
            #pragma unroll
            for (int t = 0; t < 4; t++)
                #pragma unroll
                for (int i = 0; i < 4; i++) acc[t][i] = 0.f;
            #pragma unroll
            for (int kk = 0; kk < 8; kk++) {
                const int o = 8*kk + 2*tig;
                uint2 L0 = *(const uint2*)&psI[(m0+gid)*S64   + o];
                uint2 L1 = *(const uint2*)&psI[(m0+gid+8)*S64 + o];
                #pragma unroll
                for (int t = 0; t < 4; t++) {
                    uint2 B = *(const uint2*)&xkI[(nb+8*t+gid)*S64 + o];
                    mma8(acc[t], L0.x, L1.x, L0.y, L1.y, B.x, B.y);
                }
            }
            const int cm  = koff(m0 + gid);
            const int cm8 = cm + 8;
            #pragma unroll
            for (int t = 0; t < 4; t++) {
                const int n0 = nb + 8*t + 2*tig;
                float v0 = tf32r(fmaxf(acc[t][0], 0.f) + EPSF);
                float v1 = tf32r(fmaxf(acc[t][1], 0.f) + EPSF);
                float v2 = tf32r(fmaxf(acc[t][2], 0.f) + EPSF);
                float v3 = tf32r(fmaxf(acc[t][3], 0.f) + EPSF);
                const int cn = koff(n0);            // koff(n0+1) = cn+2
                kpA[(m0+gid)*S64   + cn]   = v0;
                kpA[(m0+gid)*S64   + cn+2] = v1;
                kpA[(m0+gid+8)*S64 + cn]   = v2;
                kpA[(m0+gid+8)*S64 + cn+2] = v3;
                kpB[n0*S128     + cm]  = v0;
                kpB[(n0+1)*S128 + cm]  = v1;
                kpB[n0*S128     + cm8] = v2;
                kpB[(n0+1)*S128 + cm8] = v3;
            }
        }
        BARSYNC(4, 512);                            // kpA/kpB complete within K-side
        // seg sums from kpB rows (conflict-free): 4 segments x 16 n
        {
            const int m = t512 & 127, sg = t512 >> 7;
            const int cm = koff(m);
            float s = 0.f;
            #pragma unroll
            for (int j = 0; j < 16; j++) s += kpB[(sg*16 + j)*S128 + cm];
            seg[sg*128 + m] = s;
        }
        BARSYNC(4, 512);                            // seg complete
        // publish z_c EARLY (before phase 2)
        if (t512 < MM) {
            g_zc[(h*NCH + c)*MM + t512] =
                seg[t512] + seg[128 + t512] + seg[256 + t512] + seg[384 + t512];
        }
        __threadfence();
        BARSYNC(4, 512);
        if (t512 == 0) atomicExch(&g_flagZ[h*NCH + c], 1);
        // join with Q-side: publish kpB/seg to Q; then straight into phase 2
        BARSYNC(3, 1024);
        // phase 2: S_c = Kp^T V [128m][64d] with 16 warps (16m x 32d each)
        {
            const int m0 = 16*(wk >> 1), dh = 32*(wk & 1);
            float acc[4][4];
            #pragma unroll
            for (int t = 0; t < 4; t++)
                #pragma unroll
                for (int i = 0; i < 4; i++) acc[t][i] = 0.f;
            #pragma unroll
            for (int kk = 0; kk < 8; kk++) {
                const int o = 8*kk + 2*tig;
                uint2 L0 = *(const uint2*)&kpA[(m0+gid)*S64   + o];
                uint2 L1 = *(const uint2*)&kpA[(m0+gid+8)*S64 + o];
                #pragma unroll
                for (int t = 0; t < 4; t++) {
                    uint2 B = *(const uint2*)&vI[(dh+8*t+gid)*S64 + o];
                    mma8(acc[t], L0.x, L1.x, L0.y, L1.y, B.x, B.y);
                }
            }
            float* Sg = g_Sc + ((h*NCH + c) << 13);
            #pragma unroll
            for (int t = 0; t < 4; t++) {
                const int d0 = dh + 8*t;
                *(u64*)&Sg[(m0+gid)*64   + d0 + 2*tig] = pk2(acc[t][0], acc[t][1]);
                *(u64*)&Sg[(m0+gid+8)*64 + d0 + 2*tig] = pk2(acc[t][2], acc[t][3]);
            }
        }
        __threadfence();
        BARSYNC(4, 512);
        if (t512 == 0) atomicExch(&g_flagS[h*NCH + c], 1);
        // poll earlier S-flags, then K-side alone accumulates S_prev
        if (t512 < c) {
            while (atomicAdd(&g_flagS[h*NCH + t512], 0) == 0) {}
        }
        BARSYNC(4, 512);
        __threadfence();
        {
            const int i0 = t512 * 16;               // 16 floats per thread of [128m][64d]
            const int m = i0 >> 6, d0 = i0 & 63;
            float4 a0 = {0,0,0,0}, a1 = {0,0,0,0}, a2 = {0,0,0,0}, a3 = {0,0,0,0};
            int c2 = 0;
            for (; c2 + 1 < c; c2 += 2) {           // unroll x2: independent L2 loads
                const float4* p = (const float4*)(g_Sc + ((h*NCH + c2) << 13) + i0);
                const float4* r = (const float4*)(g_Sc + ((h*NCH + c2 + 1) << 13) + i0);
                float4 t0 = p[0], t1 = p[1], t2 = p[2], t3 = p[3];
                float4 u0 = r[0], u1 = r[1], u2 = r[2], u3 = r[3];
                a0.x += t0.x + u0.x; a0.y += t0.y + u0.y; a0.z += t0.z + u0.z; a0.w += t0.w + u0.w;
                a1.x += t1.x + u1.x; a1.y += t1.y + u1.y; a1.z += t1.z + u1.z; a1.w += t1.w + u1.w;
                a2.x += t2.x + u2.x; a2.y += t2.y + u2.y; a2.z += t2.z + u2.z; a2.w += t2.w + u2.w;
                a3.x += t3.x + u3.x; a3.y += t3.y + u3.y; a3.z += t3.z + u3.z; a3.w += t3.w + u3.w;
            }
            if (c2 < c) {
                const float4* p = (const float4*)(g_Sc + ((h*NCH + c2) << 13) + i0);
                float4 t0 = p[0], t1 = p[1], t2 = p[2], t3 = p[3];
                a0.x += t0.x; a0.y += t0.y; a0.z += t0.z; a0.w += t0.w;
                a1.x += t1.x; a1.y += t1.y; a1.z += t1.z; a1.w += t1.w;
                a2.x += t2.x; a2.y += t2.y; a2.z += t2.z; a2.w += t2.w;
                a3.x += t3.x; a3.y += t3.y; a3.z += t3.z; a3.w += t3.w;
            }
            const int cm = koff(m);
            float* dst = &SsI[d0*S128 + cm];
            dst[0*S128]=tf32r(a0.x);  dst[1*S128]=tf32r(a0.y);  dst[2*S128]=tf32r(a0.z);  dst[3*S128]=tf32r(a0.w);
            dst[4*S128]=tf32r(a1.x);  dst[5*S128]=tf32r(a1.y);  dst[6*S128]=tf32r(a1.z);  dst[7*S128]=tf32r(a1.w);
            dst[8*S128]=tf32r(a2.x);  dst[9*S128]=tf32r(a2.y);  dst[10*S128]=tf32r(a2.z); dst[11*S128]=tf32r(a2.w);
            dst[12*S128]=tf32r(a3.x); dst[13*S128]=tf32r(a3.y); dst[14*S128]=tf32r(a3.z); dst[15*S128]=tf32r(a3.w);
        }
        BARSYNC(4, 512);                            // SsI complete within K-side
        BARSYNC(6, 1024);                           // wait for qI from Q-side
        // ---- out2 = Q' @ S_prev (mma, k=m, 16 steps) ----
        {
            const int n0 = 16*(wk & 3), dp = wk >> 2;
            float acc[2][4];
            #pragma unroll
            for (int t = 0; t < 2; t++)
                #pragma unroll
                for (int i = 0; i < 4; i++) acc[t][i] = 0.f;
            #pragma unroll 4
            for (int kk = 0; kk < 16; kk++) {
                const int o = 8*kk + 2*tig;
                uint2 L0 = *(const uint2*)&qI[(n0+gid)*S128   + o];
                uint2 L1 = *(const uint2*)&qI[(n0+gid+8)*S128 + o];
                #pragma unroll
                for (int t = 0; t < 2; t++) {
                    const int d0 = 16*dp + 8*t;
                    uint2 B = *(const uint2*)&SsI[(d0+gid)*S128 + o];
                    mma8(acc[t], L0.x, L1.x, L0.y, L1.y, B.x, B.y);
                }
            }
            #pragma unroll
            for (int t = 0; t < 2; t++) {
                const int d0 = 16*dp + 8*t;
                *(u64*)&ob[(n0+gid)*72   + d0 + 2*tig] = pk2(acc[t][0], acc[t][1]);
                *(u64*)&ob[(n0+gid+8)*72 + d0 + 2*tig] = pk2(acc[t][2], acc[t][3]);
            }
        }
    }
    __syncthreads();

    // ============ phase 6: out = A @ V + out2 (mma, k=j, C-init from ob) ============
    {
        const int n0 = 16*(w & 3), d0 = 8*(w >> 2);
        float acc[4];
        float2 lo = *(const float2*)&ob[(n0+gid)*72   + d0 + 2*tig];
        float2 hi = *(const float2*)&ob[(n0+gid+8)*72 + d0 + 2*tig];
        acc[0] = lo.x; acc[1] = lo.y; acc[2] = hi.x; acc[3] = hi.y;
        #pragma unroll
        for (int kk = 0; kk < 8; kk++) {
            const int o = 8*kk + 2*tig;
            uint2 L0 = *(const uint2*)&AsI[(n0+gid)*S64   + o];
            uint2 L1 = *(const uint2*)&AsI[(n0+gid+8)*S64 + o];
            uint2 B  = *(const uint2*)&vI[(d0+gid)*S64 + o];
            mma8(acc, L0.x, L1.x, L0.y, L1.y, B.x, B.y);
        }
        float2 o0; o0.x = acc[0]; o0.y = acc[1];
        float2 o1; o1.x = acc[2]; o1.y = acc[3];
        *(float2*)&out[base + (n0+gid)*64   + d0 + 2*tig] = o0;
        *(float2*)&out[base + (n0+gid+8)*64 + d0 + 2*tig] = o1;
    }
}

// ============================================================
extern "C" void kernel_launch(void* const* d_in, const int* in_sizes, int n_in,
                              void* d_out, int out_size) {
    const float* q    = (const float*)d_in[0];
    const float* k    = (const float*)d_in[1];
    const float* v    = (const float*)d_in[2];
    const float* proj = (const float*)d_in[3];
    float* out = (float*)d_out;

    const size_t smem = SMEMF * sizeof(float);   // 204800 B
    cudaFuncSetAttribute(k_fused, cudaFuncAttributeMaxDynamicSharedMemorySize, (int)smem);
    k_fused<<<dim3(NCH, HH), 1024, smem>>>(q, k, v, proj, out);
}

// round 15
// speedup vs baseline: 1.0843x; 1.0843x over previous
#include <cuda_runtime.h>

typedef unsigned long long u64;
typedef unsigned int uint32;

#define HH 8
#define NNS 1024
#define DD 64
#define MM 128
#define CC 64
#define NCH 16
#define EPSF 1e-3f
#define NORMF 0.35355339059327373f   // 64^-0.25

// ---- global scratch ----
__device__ float g_Sc[HH*NCH*MM*DD];   // per-chunk Kp^T V (fp32, 4 MB)
__device__ float g_zc[HH*NCH*MM];      // per-chunk kp column sums
__device__ int   g_flagZ[HH*NCH];      // z_c published (zero-init; deterministic re-publish)
__device__ int   g_flagS[HH*NCH];      // S_c published

// strides: ≡ 8 (mod 32) -> uint2 fragment loads are bank-conflict-free
#define S128 136
#define S64  72

// ---- smem layout (float offsets) ----
#define OFF_QI   0                     // q'  [n=64][off128(m)]   8704
#define OFF_KPA  8704                  // kp  [m=128][off64(n)]   9216 -> 17920
#define OFF_KPB  17920                 // kp  [n=64][off128(m)]   8704 -> 26624
#define OFF_VI   26624                 // v   [d=64][off64(n)]    4608 -> 31232
#define OFF_SEG  31232                 // seg sums [4][128]        512 -> 32256 (alloc 1024)
#define OFF_ZQ   32256                 // z prefix partials [4][128] 512 -> 32768
#define OFF_D    32768
// phase1 view:
#define OFF_PSI  (OFF_D)               // proj [m=128][off64(d)]  9216
#define OFF_XQI  (OFF_D+9216)          // q*norm [n=64][off64(d)] 4608
#define OFF_XKI  (OFF_D+13824)         // k*norm [n=64][off64(d)] 4608
// post-join view:
#define OFF_SSI  (OFF_D)               // S_prev [d=64][off128(m)] 8704
#define OFF_ASI  (OFF_D+8704)          // A [n=64][off64(j)]      4608
#define OFF_OB   (OFF_D+13312)         // out2 [64][72]           4608
#define SMEMF    (OFF_D+18432)         // 51200 floats = 204800 B

#define F2U __float_as_uint
#define U2F __uint_as_float

#define BARSYNC(id, cnt) asm volatile("bar.sync %0, %1;" :: "r"(id), "r"(cnt) : "memory")

__device__ __forceinline__ int koff(int k) {
    return ((k >> 3) << 3) | ((k & 3) << 1) | ((k >> 2) & 1);
}
__device__ __forceinline__ float tf32r(float f) {
    uint32 u; asm("cvt.rna.tf32.f32 %0,%1;" : "=r"(u) : "f"(f));
    return U2F(u);
}
__device__ __forceinline__ u64 pk2(float x, float y) {
    u64 r; asm("mov.b64 %0,{%1,%2};" : "=l"(r) : "f"(x), "f"(y)); return r;
}
// D += A*B  (m16n8k8, row.col, tf32 in / f32 acc)
__device__ __forceinline__ void mma8(float* c, uint32 a0, uint32 a1, uint32 a2, uint32 a3,
                                     uint32 b0, uint32 b1) {
    asm volatile("mma.sync.aligned.m16n8k8.row.col.f32.tf32.tf32.f32 "
        "{%0,%1,%2,%3},{%4,%5,%6,%7},{%8,%9},{%0,%1,%2,%3};"
        : "+f"(c[0]), "+f"(c[1]), "+f"(c[2]), "+f"(c[3])
        : "r"(a0), "r"(a1), "r"(a2), "r"(a3), "r"(b0), "r"(b1));
}

__global__ void __launch_bounds__(1024, 1)
k_fused(const float* __restrict__ q, const float* __restrict__ k,
        const float* __restrict__ v, const float* __restrict__ proj,
        float* __restrict__ out) {
    extern __shared__ float sm[];
    const int c = blockIdx.x, h = blockIdx.y, tid = threadIdx.x;

    float* qI  = sm + OFF_QI;
    float* kpA = sm + OFF_KPA;
    float* kpB = sm + OFF_KPB;
    float* vI  = sm + OFF_VI;
    float* seg = sm + OFF_SEG;
    float* zq  = sm + OFF_ZQ;
    float* psI = sm + OFF_PSI;
    float* xqI = sm + OFF_XQI;
    float* xkI = sm + OFF_XKI;
    float* SsI = sm + OFF_SSI;
    float* AsI = sm + OFF_ASI;
    float* ob  = sm + OFF_OB;

    const int base = (h*NNS + c*CC)*DD;
    const int w = tid >> 5, lane = tid & 31;
    const int gid = lane >> 2, tig = lane & 3;

    // ================= phase 0: loads (tf32-rounded, interleaved) =================
    for (int i = tid; i < MM*DD; i += 1024) {
        int m = i >> 6, d = i & 63;
        psI[m*S64 + koff(d)] = tf32r(proj[i]);
    }
    for (int i = tid; i < CC*DD; i += 1024) {
        int n = i >> 6, d = i & 63;
        xqI[n*S64 + koff(d)] = tf32r(q[base + i] * NORMF);
        xkI[n*S64 + koff(d)] = tf32r(k[base + i] * NORMF);
        vI[d*S64 + koff(n)]  = tf32r(v[base + i]);
    }
    __syncthreads();

    // =================== warp-specialized middle section ===================
    if (w < 16) {
        // ---------------- Q-side (warps 0-15, tids 0-511) ----------------
        // phase 1q: qp[m][n] -> qI [n][off128(m)]
        {
            const int m0 = 16*(w >> 1), nb = 32*(w & 1);
            float acc[4][4];
            #pragma unroll
            for (int t = 0; t < 4; t++)
                #pragma unroll
                for (int i = 0; i < 4; i++) acc[t][i] = 0.f;
            #pragma unroll
            for (int kk = 0; kk < 8; kk++) {
                const int o = 8*kk + 2*tig;
                uint2 L0 = *(const uint2*)&psI[(m0+gid)*S64   + o];
                uint2 L1 = *(const uint2*)&psI[(m0+gid+8)*S64 + o];
                #pragma unroll
                for (int t = 0; t < 4; t++) {
                    uint2 B = *(const uint2*)&xqI[(nb+8*t+gid)*S64 + o];
                    mma8(acc[t], L0.x, L1.x, L0.y, L1.y, B.x, B.y);
                }
            }
            const int cm  = koff(m0 + gid);
            const int cm8 = cm + 8;
            #pragma unroll
            for (int t = 0; t < 4; t++) {
                const int n0 = nb + 8*t + 2*tig;
                qI[n0*S128     + cm]  = tf32r(fmaxf(acc[t][0], 0.f) + EPSF);
                qI[(n0+1)*S128 + cm]  = tf32r(fmaxf(acc[t][1], 0.f) + EPSF);
                qI[n0*S128     + cm8] = tf32r(fmaxf(acc[t][2], 0.f) + EPSF);
                qI[(n0+1)*S128 + cm8] = tf32r(fmaxf(acc[t][3], 0.f) + EPSF);
            }
        }
        // join with K-side: kpB + seg ready after this; K proceeds to phase 2
        BARSYNC(3, 1024);
        // poll z-flags of earlier chunks (set before their phase 2)
        if (tid < c) {
            while (atomicAdd(&g_flagZ[h*NCH + tid], 0) == 0) {}
        }
        BARSYNC(5, 512);
        __threadfence();
        // z prefix (4-way over 512 threads)
        {
            const int m = tid & 127, qtr = tid >> 7;
            float z = 0.f;
            for (int c2 = qtr; c2 < c; c2 += 4)
                z += g_zc[(h*NCH + c2)*MM + m];
            zq[qtr*128 + m] = z;
        }
        BARSYNC(5, 512);
        // ordered cumsum + divide: 4 segments x 16 n (kpB rows: conflict-free)
        {
            const int m = tid & 127, qtr = tid >> 7;
            const int cm = koff(m);
            float run = zq[m] + zq[128 + m] + zq[256 + m] + zq[384 + m];
            #pragma unroll
            for (int s = 0; s < 3; s++)
                if (s < qtr) run += seg[s*128 + m];
            #pragma unroll
            for (int j = 0; j < 16; j++) {
                const int n = qtr*16 + j;
                run += kpB[n*S128 + cm];
                qI[n*S128 + cm] = tf32r(__fdividef(qI[n*S128 + cm], run));
            }
        }
    } else {
        // ---------------- K-side (warps 16-31, tids 512-1023) ----------------
        const int wk = w - 16;
        const int t512 = tid - 512;
        // phase 1k: kp[m][n] -> kpA [m][off64(n)] and kpB [n][off128(m)]
        {
            const int m0 = 16*(wk >> 1), nb = 32*(wk & 1);
            float acc[4][4];
            #pragma unroll
            for (int t = 0; t < 4; t++)
                #pragma unroll
                for (int i = 0; i < 4; i++) acc[t][i] = 0.f;
            #pragma unroll
            for (int kk = 0; kk < 8; kk++) {
                const int o = 8*kk + 2*tig;
                uint2 L0 = *(const uint2*)&psI[(m0+gid)*S64   + o];
                uint2 L1 = *(const uint2*)&psI[(m0+gid+8)*S64 + o];
                #pragma unroll
                for (int t = 0; t < 4; t++) {
                    uint2 B = *(const uint2*)&xkI[(nb+8*t+gid)*S64 + o];
                    mma8(acc[t], L0.x, L1.x, L0.y, L1.y, B.x, B.y);
                }
            }
            const int cm  = koff(m0 + gid);
            const int cm8 = cm + 8;
            #pragma unroll
            for (int t = 0; t < 4; t++) {
                const int n0 = nb + 8*t + 2*tig;
                float v0 = tf32r(fmaxf(acc[t][0], 0.f) + EPSF);
                float v1 = tf32r(fmaxf(acc[t][1], 0.f) + EPSF);
                float v2 = tf32r(fmaxf(acc[t][2], 0.f) + EPSF);
                float v3 = tf32r(fmaxf(acc[t][3], 0.f) + EPSF);
                const int cn = koff(n0);            // koff(n0+1) = cn+2
                kpA[(m0+gid)*S64   + cn]   = v0;
                kpA[(m0+gid)*S64   + cn+2] = v1;
                kpA[(m0+gid+8)*S64 + cn]   = v2;
                kpA[(m0+gid+8)*S64 + cn+2] = v3;
                kpB[n0*S128     + cm]  = v0;
                kpB[(n0+1)*S128 + cm]  = v1;
                kpB[n0*S128     + cm8] = v2;
                kpB[(n0+1)*S128 + cm8] = v3;
            }
        }
        BARSYNC(4, 512);                            // kpA/kpB complete within K-side
        // seg sums from kpB rows (conflict-free): 4 segments x 16 n
        {
            const int m = t512 & 127, sg = t512 >> 7;
            const int cm = koff(m);
            float s = 0.f;
            #pragma unroll
            for (int j = 0; j < 16; j++) s += kpB[(sg*16 + j)*S128 + cm];
            seg[sg*128 + m] = s;
        }
        BARSYNC(4, 512);                            // seg complete
        // publish z_c EARLY (before phase 2)
        if (t512 < MM) {
            g_zc[(h*NCH + c)*MM + t512] =
                seg[t512] + seg[128 + t512] + seg[256 + t512] + seg[384 + t512];
        }
        __threadfence();
        BARSYNC(4, 512);
        if (t512 == 0) atomicExch(&g_flagZ[h*NCH + c], 1);
        // join with Q-side: publish kpB/seg to Q; then straight into phase 2
        BARSYNC(3, 1024);
        // phase 2: S_c = Kp^T V [128m][64d] with 16 warps (16m x 32d each)
        {
            const int m0 = 16*(wk >> 1), dh = 32*(wk & 1);
            float acc[4][4];
            #pragma unroll
            for (int t = 0; t < 4; t++)
                #pragma unroll
                for (int i = 0; i < 4; i++) acc[t][i] = 0.f;
            #pragma unroll
            for (int kk = 0; kk < 8; kk++) {
                const int o = 8*kk + 2*tig;
                uint2 L0 = *(const uint2*)&kpA[(m0+gid)*S64   + o];
                uint2 L1 = *(const uint2*)&kpA[(m0+gid+8)*S64 + o];
                #pragma unroll
                for (int t = 0; t < 4; t++) {
                    uint2 B = *(const uint2*)&vI[(dh+8*t+gid)*S64 + o];
                    mma8(acc[t], L0.x, L1.x, L0.y, L1.y, B.x, B.y);
                }
            }
            float* Sg = g_Sc + ((h*NCH + c) << 13);
            #pragma unroll
            for (int t = 0; t < 4; t++) {
                const int d0 = dh + 8*t;
                *(u64*)&Sg[(m0+gid)*64   + d0 + 2*tig] = pk2(acc[t][0], acc[t][1]);
                *(u64*)&Sg[(m0+gid+8)*64 + d0 + 2*tig] = pk2(acc[t][2], acc[t][3]);
            }
        }
        __threadfence();
        BARSYNC(4, 512);
        if (t512 == 0) atomicExch(&g_flagS[h*NCH + c], 1);
    }

    // ========== common: poll S-flags, then ALL 1024 threads accumulate S_prev ==========
    {
        const int cc2 = tid & 511;
        if (cc2 < c) {
            while (atomicAdd(&g_flagS[h*NCH + cc2], 0) == 0) {}
        }
    }
    __syncthreads();
    __threadfence();
    {
        const int i0 = tid * 8;                     // 8 floats per thread of [128m][64d]
        const int m = i0 >> 6, d0 = i0 & 63;
        float4 a0 = {0,0,0,0}, a1 = {0,0,0,0};
        float4 b0 = {0,0,0,0}, b1 = {0,0,0,0};      // second accumulator pair (MLP)
        int c2 = 0;
        for (; c2 + 1 < c; c2 += 2) {               // unroll x2: 4 independent L2 loads
            const float4* p = (const float4*)(g_Sc + ((h*NCH + c2) << 13) + i0);
            const float4* r = (const float4*)(g_Sc + ((h*NCH + c2 + 1) << 13) + i0);
            float4 t0 = p[0], t1 = p[1];
            float4 u0 = r[0], u1 = r[1];
            a0.x += t0.x; a0.y += t0.y; a0.z += t0.z; a0.w += t0.w;
            a1.x += t1.x; a1.y += t1.y; a1.z += t1.z; a1.w += t1.w;
            b0.x += u0.x; b0.y += u0.y; b0.z += u0.z; b0.w += u0.w;
            b1.x += u1.x; b1.y += u1.y; b1.z += u1.z; b1.w += u1.w;
        }
        if (c2 < c) {
            const float4* p = (const float4*)(g_Sc + ((h*NCH + c2) << 13) + i0);
            float4 t0 = p[0], t1 = p[1];
            a0.x += t0.x; a0.y += t0.y; a0.z += t0.z; a0.w += t0.w;
            a1.x += t1.x; a1.y += t1.y; a1.z += t1.z; a1.w += t1.w;
        }
        a0.x += b0.x; a0.y += b0.y; a0.z += b0.z; a0.w += b0.w;
        a1.x += b1.x; a1.y += b1.y; a1.z += b1.z; a1.w += b1.w;
        const int cm = koff(m);
        float* dst = &SsI[d0*S128 + cm];
        dst[0*S128]=tf32r(a0.x); dst[1*S128]=tf32r(a0.y); dst[2*S128]=tf32r(a0.z); dst[3*S128]=tf32r(a0.w);
        dst[4*S128]=tf32r(a1.x); dst[5*S128]=tf32r(a1.y); dst[6*S128]=tf32r(a1.z); dst[7*S128]=tf32r(a1.w);
    }
    __syncthreads();

    // ============ phase 5: A = tril(Q'Kp^T) | out2 = Q'S_prev (mma, k=m, 16 steps) ============
    if (w < 16) {
        const int nq = w & 3, jp = w >> 2;
        const int n0 = 16*nq;
        if (jp > nq) {
            // tile entirely above diagonal: zeros, skip GEMM
            #pragma unroll
            for (int t = 0; t < 2; t++) {
                const int j = 16*jp + 8*t + 2*tig;
                const int cj = koff(j);
                const int n1 = n0 + gid, n2 = n1 + 8;
                AsI[n1*S64 + cj]   = 0.f;  AsI[n1*S64 + cj+2] = 0.f;
                AsI[n2*S64 + cj]   = 0.f;  AsI[n2*S64 + cj+2] = 0.f;
            }
        } else {
            float acc[2][4];
            #pragma unroll
            for (int t = 0; t < 2; t++)
                #pragma unroll
                for (int i = 0; i < 4; i++) acc[t][i] = 0.f;
            #pragma unroll 4
            for (int kk = 0; kk < 16; kk++) {
                const int o = 8*kk + 2*tig;
                uint2 L0 = *(const uint2*)&qI[(n0+gid)*S128   + o];
                uint2 L1 = *(const uint2*)&qI[(n0+gid+8)*S128 + o];
                #pragma unroll
                for (int t = 0; t < 2; t++) {
                    const int j0 = 16*jp + 8*t;
                    uint2 B = *(const uint2*)&kpB[(j0+gid)*S128 + o];
                    mma8(acc[t], L0.x, L1.x, L0.y, L1.y, B.x, B.y);
                }
            }
            if (jp < nq) {
                // tile entirely below diagonal: no masking needed
                #pragma unroll
                for (int t = 0; t < 2; t++) {
                    const int j = 16*jp + 8*t + 2*tig;
                    const int cj = koff(j);
                    const int n1 = n0 + gid, n2 = n1 + 8;
                    AsI[n1*S64 + cj]   = tf32r(acc[t][0]);
                    AsI[n1*S64 + cj+2] = tf32r(acc[t][1]);
                    AsI[n2*S64 + cj]   = tf32r(acc[t][2]);
                    AsI[n2*S64 + cj+2] = tf32r(acc[t][3]);
                }
            } else {
                // diagonal tile: per-element causal mask
                #pragma unroll
                for (int t = 0; t < 2; t++) {
                    const int j = 16*jp + 8*t + 2*tig;
                    const int n1 = n0 + gid, n2 = n1 + 8;
                    const int cj = koff(j);
                    AsI[n1*S64 + cj]   = (j   <= n1) ? tf32r(acc[t][0]) : 0.f;
                    AsI[n1*S64 + cj+2] = (j+1 <= n1) ? tf32r(acc[t][1]) : 0.f;
                    AsI[n2*S64 + cj]   = (j   <= n2) ? tf32r(acc[t][2]) : 0.f;
                    AsI[n2*S64 + cj+2] = (j+1 <= n2) ? tf32r(acc[t][3]) : 0.f;
                }
            }
        }
    } else {
        const int wl = w - 16;
        const int n0 = 16*(wl & 3), dp = wl >> 2;
        float acc[2][4];
        #pragma unroll
        for (int t = 0; t < 2; t++)
            #pragma unroll
            for (int i = 0; i < 4; i++) acc[t][i] = 0.f;
        #pragma unroll 4
        for (int kk = 0; kk < 16; kk++) {
            const int o = 8*kk + 2*tig;
            uint2 L0 = *(const uint2*)&qI[(n0+gid)*S128   + o];
            uint2 L1 = *(const uint2*)&qI[(n0+gid+8)*S128 + o];
            #pragma unroll
            for (int t = 0; t < 2; t++) {
                const int d0 = 16*dp + 8*t;
                uint2 B = *(const uint2*)&SsI[(d0+gid)*S128 + o];
                mma8(acc[t], L0.x, L1.x, L0.y, L1.y, B.x, B.y);
            }
        }
        #pragma unroll
        for (int t = 0; t < 2; t++) {
            const int d0 = 16*dp + 8*t;
            *(u64*)&ob[(n0+gid)*72   + d0 + 2*tig] = pk2(acc[t][0], acc[t][1]);
            *(u64*)&ob[(n0+gid+8)*72 + d0 + 2*tig] = pk2(acc[t][2], acc[t][3]);
        }
    }
    __syncthreads();

    // ============ phase 6: out = A @ V + out2 (mma, k=j, C-init from ob) ============
    {
        const int n0 = 16*(w & 3), d0 = 8*(w >> 2);
        float acc[4];
        float2 lo = *(const float2*)&ob[(n0+gid)*72   + d0 + 2*tig];
        float2 hi = *(const float2*)&ob[(n0+gid+8)*72 + d0 + 2*tig];
        acc[0] = lo.x; acc[1] = lo.y; acc[2] = hi.x; acc[3] = hi.y;
        #pragma unroll
        for (int kk = 0; kk < 8; kk++) {
            const int o = 8*kk + 2*tig;
            uint2 L0 = *(const uint2*)&AsI[(n0+gid)*S64   + o];
            uint2 L1 = *(const uint2*)&AsI[(n0+gid+8)*S64 + o];
            uint2 B  = *(const uint2*)&vI[(d0+gid)*S64 + o];
            mma8(acc, L0.x, L1.x, L0.y, L1.y, B.x, B.y);
        }
        float2 o0; o0.x = acc[0]; o0.y = acc[1];
        float2 o1; o1.x = acc[2]; o1.y = acc[3];
        *(float2*)&out[base + (n0+gid)*64   + d0 + 2*tig] = o0;
        *(float2*)&out[base + (n0+gid+8)*64 + d0 + 2*tig] = o1;
    }
}

// ============================================================
extern "C" void kernel_launch(void* const* d_in, const int* in_sizes, int n_in,
                              void* d_out, int out_size) {
    const float* q    = (const float*)d_in[0];
    const float* k    = (const float*)d_in[1];
    const float* v    = (const float*)d_in[2];
    const float* proj = (const float*)d_in[3];
    float* out = (float*)d_out;

    const size_t smem = SMEMF * sizeof(float);   // 204800 B
    cudaFuncSetAttribute(k_fused, cudaFuncAttributeMaxDynamicSharedMemorySize, (int)smem);
    k_fused<<<dim3(NCH, HH), 1024, smem>>>(q, k, v, proj, out);
}